// round 10
// baseline (speedup 1.0000x reference)
#include <cuda_runtime.h>
#include <cstdint>

#define B_  4
#define L_  2048
#define D_  1024
#define H_  16
#define DK_ 64
#define M_  (B_*L_)   // 8192

// Scratch (device globals — no allocation allowed)
__device__ float g_Qp[M_*D_];
__device__ float g_Kp[M_*D_];
__device__ float g_Vp[M_*D_];
__device__ float g_Ao[M_*D_];

__device__ __forceinline__ uint32_t f2tf32(float f) {
    uint32_t r;
    asm("cvt.rna.tf32.f32 %0, %1;" : "=r"(r) : "f"(f));
    return r;
}
__device__ __forceinline__ float tf32r(float f) {
    return __uint_as_float(f2tf32(f));
}

// ---------------------------------------------------------------------------
// TF32 tensor-core GEMM: Y = (X W^T + bias) * scale, optionally tf32-rounded.
// M=8192, N=1024, K=1024. 128x128 tile, BK=16, 256 thr, cp.async double buffer.
// ---------------------------------------------------------------------------
__global__ __launch_bounds__(256)
void gemm_tf32_nt_bias(const float* __restrict__ X, const float* __restrict__ W,
                       const float* __restrict__ bias, float* __restrict__ Y,
                       int round_out, float scale) {
    __shared__ float As[2][128][20];
    __shared__ float Bs[2][128][20];

    const int tid  = threadIdx.x;
    const int m0   = blockIdx.y * 128;
    const int n0   = blockIdx.x * 128;
    const int warp = tid >> 5;
    const int lane = tid & 31;
    const int wm   = warp >> 2;
    const int wn   = warp & 3;
    const int g    = lane >> 2;
    const int tg   = lane & 3;

    const int lr = tid >> 2;
    const int sg = (tid & 3) * 4;

    float c[4][4][4];
#pragma unroll
    for (int mt = 0; mt < 4; mt++)
#pragma unroll
        for (int nt = 0; nt < 4; nt++)
#pragma unroll
            for (int e = 0; e < 4; e++) c[mt][nt][e] = 0.f;

#define ISSUE_STAGE(KT, BUF)                                                     \
    do {                                                                         \
        const int _k0 = (KT) * 16;                                               \
        _Pragma("unroll")                                                        \
        for (int _i = 0; _i < 2; _i++) {                                         \
            const int _row = lr + _i * 64;                                       \
            const float* _gx = X + (size_t)(m0 + _row) * D_ + _k0 + sg;          \
            uint32_t _sa = (uint32_t)__cvta_generic_to_shared(&As[BUF][_row][sg]);\
            asm volatile("cp.async.cg.shared.global [%0], [%1], 16;"             \
                         :: "r"(_sa), "l"(_gx));                                 \
            const float* _gw = W + (size_t)(n0 + _row) * D_ + _k0 + sg;          \
            uint32_t _sb = (uint32_t)__cvta_generic_to_shared(&Bs[BUF][_row][sg]);\
            asm volatile("cp.async.cg.shared.global [%0], [%1], 16;"             \
                         :: "r"(_sb), "l"(_gw));                                 \
        }                                                                        \
        asm volatile("cp.async.commit_group;");                                  \
    } while (0)

    ISSUE_STAGE(0, 0);

    const int NKT = D_ / 16;
    for (int kt = 0; kt < NKT; kt++) {
        asm volatile("cp.async.wait_group 0;");
        __syncthreads();
        if (kt + 1 < NKT) ISSUE_STAGE(kt + 1, (kt + 1) & 1);

        const int buf = kt & 1;
#pragma unroll
        for (int s = 0; s < 2; s++) {
            const int kk = s * 8;
            uint32_t a[4][4], b[4][2];
#pragma unroll
            for (int mt = 0; mt < 4; mt++) {
                const int row = wm * 64 + mt * 16 + g;
                a[mt][0] = f2tf32(As[buf][row    ][kk + tg    ]);
                a[mt][1] = f2tf32(As[buf][row + 8][kk + tg    ]);
                a[mt][2] = f2tf32(As[buf][row    ][kk + tg + 4]);
                a[mt][3] = f2tf32(As[buf][row + 8][kk + tg + 4]);
            }
#pragma unroll
            for (int nt = 0; nt < 4; nt++) {
                const int col = wn * 32 + nt * 8 + g;
                b[nt][0] = f2tf32(Bs[buf][col][kk + tg    ]);
                b[nt][1] = f2tf32(Bs[buf][col][kk + tg + 4]);
            }
#pragma unroll
            for (int mt = 0; mt < 4; mt++)
#pragma unroll
                for (int nt = 0; nt < 4; nt++) {
                    asm volatile(
                        "mma.sync.aligned.m16n8k8.row.col.f32.tf32.tf32.f32 "
                        "{%0,%1,%2,%3}, {%4,%5,%6,%7}, {%8,%9}, {%0,%1,%2,%3};"
                        : "+f"(c[mt][nt][0]), "+f"(c[mt][nt][1]),
                          "+f"(c[mt][nt][2]), "+f"(c[mt][nt][3])
                        : "r"(a[mt][0]), "r"(a[mt][1]), "r"(a[mt][2]), "r"(a[mt][3]),
                          "r"(b[nt][0]), "r"(b[nt][1]));
                }
        }
        __syncthreads();
    }
#undef ISSUE_STAGE

#pragma unroll
    for (int nt = 0; nt < 4; nt++) {
        const int col = n0 + wn * 32 + nt * 8 + tg * 2;
        const float2 bv = *(const float2*)&bias[col];
#pragma unroll
        for (int mt = 0; mt < 4; mt++) {
            const int row = m0 + wm * 64 + mt * 16 + g;
            float2 o0, o1;
            o0.x = (c[mt][nt][0] + bv.x) * scale;
            o0.y = (c[mt][nt][1] + bv.y) * scale;
            o1.x = (c[mt][nt][2] + bv.x) * scale;
            o1.y = (c[mt][nt][3] + bv.y) * scale;
            if (round_out) {
                o0.x = tf32r(o0.x); o0.y = tf32r(o0.y);
                o1.x = tf32r(o1.x); o1.y = tf32r(o1.y);
            }
            *(float2*)(Y + (size_t)row * D_ + col)       = o0;
            *(float2*)(Y + (size_t)(row + 8) * D_ + col) = o1;
        }
    }
}

// ---------------------------------------------------------------------------
// Flash attention, causal, TF32 tensor cores, cp.async double-buffered K/V.
// Inputs are pre-rounded to tf32 (and Q pre-scaled by 0.125) by the GEMMs.
// Grid: (L/128, H, B), 256 threads = 8 warps; warp w owns q-rows [w*16, w*16+16).
// Smem: Qs[128][68], Ks[2][64][68] natural [c][d], Vs[2][64][72] natural [c][d].
//   Pitches: 68 -> bank 4g+tg (injective) for Q/K fragment loads;
//            72 -> bank 8tg+g (injective) for V fragment loads.
// P never touches smem: S-accum fragments are transposed to A-operand
// fragments with quad-width shuffles.
// ---------------------------------------------------------------------------
#define PQ  68
#define PV  72
#define FLASH_SMEM_FLOATS (128*PQ + 2*64*PQ + 2*64*PV)
#define FLASH_SMEM_BYTES  (FLASH_SMEM_FLOATS * 4)

__device__ __forceinline__ float redmax4(float v) {
    v = fmaxf(v, __shfl_xor_sync(0xffffffffu, v, 1));
    v = fmaxf(v, __shfl_xor_sync(0xffffffffu, v, 2));
    return v;
}
__device__ __forceinline__ float redsum4(float v) {
    v += __shfl_xor_sync(0xffffffffu, v, 1);
    v += __shfl_xor_sync(0xffffffffu, v, 2);
    return v;
}

__global__ __launch_bounds__(256)
void flash_attn_tc(const float* __restrict__ Qp, const float* __restrict__ Kp,
                   const float* __restrict__ Vp, float* __restrict__ Ao) {
    extern __shared__ float sm[];
    float* Qs  = sm;                    // [128][PQ]
    float* Ksm = Qs + 128 * PQ;         // [2][64][PQ]
    float* Vsm = Ksm + 2 * 64 * PQ;     // [2][64][PV]

    const int tid  = threadIdx.x;
    const int warp = tid >> 5;
    const int lane = tid & 31;
    const int g    = lane >> 2;
    const int tg   = lane & 3;
    const int qb   = (int)gridDim.x - 1 - (int)blockIdx.x;  // heavy tiles first
    const int h    = blockIdx.y;
    const int b    = blockIdx.z;

    const int rowbase = b * L_ + qb * 128;
    const int colbase = h * DK_;
    const int wr0     = warp * 16;

    // ---- prologue: Q tile via cp.async (pre-scaled & tf32-rounded upstream) ----
    {
        const int r  = tid >> 1;
        const int cb = (tid & 1) * 32;
        const float* src = Qp + (size_t)(rowbase + r) * D_ + colbase + cb;
        uint32_t dst = (uint32_t)__cvta_generic_to_shared(Qs + r * PQ + cb);
#pragma unroll
        for (int i = 0; i < 8; i++)
            asm volatile("cp.async.cg.shared.global [%0], [%1], 16;"
                         :: "r"(dst + i * 16), "l"(src + i * 4));
    }

    const int kvc = tid >> 2;            // key row this thread loads
    const int kvs = (tid & 3) * 16;      // 16-float segment start
#define ISSUE_KV(KB, BUF)                                                        \
    do {                                                                         \
        const size_t _gr = (size_t)(b * L_ + (KB) * 64 + kvc) * D_ + colbase + kvs;\
        const float* _ks = Kp + _gr;                                             \
        const float* _vs = Vp + _gr;                                             \
        uint32_t _kd = (uint32_t)__cvta_generic_to_shared(                        \
            Ksm + (BUF) * 64 * PQ + kvc * PQ + kvs);                             \
        uint32_t _vd = (uint32_t)__cvta_generic_to_shared(                        \
            Vsm + (BUF) * 64 * PV + kvc * PV + kvs);                             \
        _Pragma("unroll")                                                        \
        for (int _i = 0; _i < 4; _i++) {                                         \
            asm volatile("cp.async.cg.shared.global [%0], [%1], 16;"             \
                         :: "r"(_kd + _i * 16), "l"(_ks + _i * 4));              \
            asm volatile("cp.async.cg.shared.global [%0], [%1], 16;"             \
                         :: "r"(_vd + _i * 16), "l"(_vs + _i * 4));              \
        }                                                                        \
    } while (0)

    ISSUE_KV(0, 0);
    asm volatile("cp.async.commit_group;");

    float m0 = -1e30f, m1 = -1e30f, l0 = 0.f, l1 = 0.f;
    float O[8][4];
#pragma unroll
    for (int dt = 0; dt < 8; dt++)
#pragma unroll
        for (int e = 0; e < 4; e++) O[dt][e] = 0.f;

    const int nkb = 2 * qb + 2;

    for (int kb = 0; kb < nkb; kb++) {
        const int buf = kb & 1;
        asm volatile("cp.async.wait_group 0;");
        __syncthreads();
        if (kb + 1 < nkb) ISSUE_KV(kb + 1, buf ^ 1);
        asm volatile("cp.async.commit_group;");

        const float* Kb = Ksm + buf * 64 * PQ;
        const float* Vb = Vsm + buf * 64 * PV;

        // ---- S = Q K^T ----
        float s[8][4];
#pragma unroll
        for (int nt = 0; nt < 8; nt++)
#pragma unroll
            for (int e = 0; e < 4; e++) s[nt][e] = 0.f;

#pragma unroll
        for (int ks = 0; ks < 8; ks++) {
            const int kk = ks * 8;
            uint32_t a0 = __float_as_uint(Qs[(wr0 + g    ) * PQ + kk + tg    ]);
            uint32_t a1 = __float_as_uint(Qs[(wr0 + g + 8) * PQ + kk + tg    ]);
            uint32_t a2 = __float_as_uint(Qs[(wr0 + g    ) * PQ + kk + tg + 4]);
            uint32_t a3 = __float_as_uint(Qs[(wr0 + g + 8) * PQ + kk + tg + 4]);
#pragma unroll
            for (int nt = 0; nt < 8; nt++) {
                uint32_t b0 = __float_as_uint(Kb[(nt*8 + g) * PQ + kk + tg    ]);
                uint32_t b1 = __float_as_uint(Kb[(nt*8 + g) * PQ + kk + tg + 4]);
                asm volatile(
                    "mma.sync.aligned.m16n8k8.row.col.f32.tf32.tf32.f32 "
                    "{%0,%1,%2,%3}, {%4,%5,%6,%7}, {%8,%9}, {%0,%1,%2,%3};"
                    : "+f"(s[nt][0]), "+f"(s[nt][1]), "+f"(s[nt][2]), "+f"(s[nt][3])
                    : "r"(a0), "r"(a1), "r"(a2), "r"(a3), "r"(b0), "r"(b1));
            }
        }

        // ---- causal mask ----
        if (kb >= 2 * qb) {
            const int qg0 = qb * 128 + wr0 + g;
            const int qg1 = qg0 + 8;
#pragma unroll
            for (int nt = 0; nt < 8; nt++) {
                const int kg = kb * 64 + nt * 8 + 2 * tg;
                if (kg     > qg0) s[nt][0] = -1e30f;
                if (kg + 1 > qg0) s[nt][1] = -1e30f;
                if (kg     > qg1) s[nt][2] = -1e30f;
                if (kg + 1 > qg1) s[nt][3] = -1e30f;
            }
        }

        // ---- online softmax; P stays in registers (tf32-rounded) ----
        {
            float mx0 = -1e30f, mx1 = -1e30f;
#pragma unroll
            for (int nt = 0; nt < 8; nt++) {
                mx0 = fmaxf(mx0, fmaxf(s[nt][0], s[nt][1]));
                mx1 = fmaxf(mx1, fmaxf(s[nt][2], s[nt][3]));
            }
            mx0 = redmax4(mx0); mx1 = redmax4(mx1);
            const float mn0 = fmaxf(m0, mx0), mn1 = fmaxf(m1, mx1);
            const float al0 = __expf(m0 - mn0), al1 = __expf(m1 - mn1);

            float sum0 = 0.f, sum1 = 0.f;
#pragma unroll
            for (int nt = 0; nt < 8; nt++) {
                const float e0 = __expf(s[nt][0] - mn0);
                const float e1 = __expf(s[nt][1] - mn0);
                const float e2 = __expf(s[nt][2] - mn1);
                const float e3 = __expf(s[nt][3] - mn1);
                sum0 += e0 + e1; sum1 += e2 + e3;
                s[nt][0] = tf32r(e0); s[nt][1] = tf32r(e1);
                s[nt][2] = tf32r(e2); s[nt][3] = tf32r(e3);
            }
            sum0 = redsum4(sum0); sum1 = redsum4(sum1);
            l0 = l0 * al0 + sum0; l1 = l1 * al1 + sum1;
            m0 = mn0; m1 = mn1;
#pragma unroll
            for (int dt = 0; dt < 8; dt++) {
                O[dt][0] *= al0; O[dt][1] *= al0;
                O[dt][2] *= al1; O[dt][3] *= al1;
            }
        }

        // ---- O += P V : transpose P chunk via quad shuffles, V from smem ----
        const int src0 = tg >> 1;
        const int src1 = (tg >> 1) + 2;
        const bool odd = (tg & 1) != 0;
#pragma unroll
        for (int ks = 0; ks < 8; ks++) {
            const float e0 = s[ks][0], e1 = s[ks][1];
            const float e2 = s[ks][2], e3 = s[ks][3];
            const float t00 = __shfl_sync(0xffffffffu, e0, src0, 4);
            const float t01 = __shfl_sync(0xffffffffu, e1, src0, 4);
            const float t10 = __shfl_sync(0xffffffffu, e0, src1, 4);
            const float t11 = __shfl_sync(0xffffffffu, e1, src1, 4);
            const float t20 = __shfl_sync(0xffffffffu, e2, src0, 4);
            const float t21 = __shfl_sync(0xffffffffu, e3, src0, 4);
            const float t30 = __shfl_sync(0xffffffffu, e2, src1, 4);
            const float t31 = __shfl_sync(0xffffffffu, e3, src1, 4);
            uint32_t a0 = __float_as_uint(odd ? t01 : t00);  // P[g   ][ks*8+tg  ]
            uint32_t a2 = __float_as_uint(odd ? t11 : t10);  // P[g   ][ks*8+tg+4]
            uint32_t a1 = __float_as_uint(odd ? t21 : t20);  // P[g+8 ][ks*8+tg  ]
            uint32_t a3 = __float_as_uint(odd ? t31 : t30);  // P[g+8 ][ks*8+tg+4]
#pragma unroll
            for (int dt = 0; dt < 8; dt++) {
                uint32_t b0 = __float_as_uint(Vb[(ks*8 + tg    ) * PV + dt*8 + g]);
                uint32_t b1 = __float_as_uint(Vb[(ks*8 + tg + 4) * PV + dt*8 + g]);
                asm volatile(
                    "mma.sync.aligned.m16n8k8.row.col.f32.tf32.tf32.f32 "
                    "{%0,%1,%2,%3}, {%4,%5,%6,%7}, {%8,%9}, {%0,%1,%2,%3};"
                    : "+f"(O[dt][0]), "+f"(O[dt][1]), "+f"(O[dt][2]), "+f"(O[dt][3])
                    : "r"(a0), "r"(a1), "r"(a2), "r"(a3), "r"(b0), "r"(b1));
            }
        }
    }
#undef ISSUE_KV

    // ---- normalize and write out ----
    {
        const float inv0 = 1.0f / l0;
        const float inv1 = 1.0f / l1;
        float* d0 = Ao + (size_t)(rowbase + wr0 + g    ) * D_ + colbase + 2 * tg;
        float* d1 = Ao + (size_t)(rowbase + wr0 + g + 8) * D_ + colbase + 2 * tg;
#pragma unroll
        for (int dt = 0; dt < 8; dt++) {
            float2 o0, o1;
            o0.x = O[dt][0] * inv0; o0.y = O[dt][1] * inv0;
            o1.x = O[dt][2] * inv1; o1.y = O[dt][3] * inv1;
            *(float2*)(d0 + dt * 8) = o0;
            *(float2*)(d1 + dt * 8) = o1;
        }
    }
}

// ---------------------------------------------------------------------------
extern "C" void kernel_launch(void* const* d_in, const int* in_sizes, int n_in,
                              void* d_out, int out_size) {
    (void)in_sizes; (void)n_in; (void)out_size;
    const float* q    = (const float*)d_in[0];
    const float* k    = (const float*)d_in[1];
    const float* v    = (const float*)d_in[2];
    const float* wq_w = (const float*)d_in[3];
    const float* wq_b = (const float*)d_in[4];
    const float* wk_w = (const float*)d_in[5];
    const float* wk_b = (const float*)d_in[6];
    const float* wv_w = (const float*)d_in[7];
    const float* wv_b = (const float*)d_in[8];
    const float* wo_w = (const float*)d_in[9];
    const float* wo_b = (const float*)d_in[10];

    float *Qp, *Kp, *Vp, *Ao;
    cudaGetSymbolAddress((void**)&Qp, g_Qp);
    cudaGetSymbolAddress((void**)&Kp, g_Kp);
    cudaGetSymbolAddress((void**)&Vp, g_Vp);
    cudaGetSymbolAddress((void**)&Ao, g_Ao);

    dim3 gg(D_/128, M_/128);   // (8, 64)
    gemm_tf32_nt_bias<<<gg, 256>>>(q, wq_w, wq_b, Qp, 1, 0.125f); // Q pre-scaled
    gemm_tf32_nt_bias<<<gg, 256>>>(k, wk_w, wk_b, Kp, 1, 1.0f);
    gemm_tf32_nt_bias<<<gg, 256>>>(v, wv_w, wv_b, Vp, 1, 1.0f);

    cudaFuncSetAttribute(flash_attn_tc,
                         cudaFuncAttributeMaxDynamicSharedMemorySize,
                         FLASH_SMEM_BYTES);
    flash_attn_tc<<<dim3(L_/128, H_, B_), 256, FLASH_SMEM_BYTES>>>(Qp, Kp, Vp, Ao);

    gemm_tf32_nt_bias<<<gg, 256>>>(Ao, wo_w, wo_b, (float*)d_out, 0, 1.0f);
}

// round 14
// speedup vs baseline: 1.8283x; 1.8283x over previous
#include <cuda_runtime.h>
#include <cuda_fp16.h>
#include <cstdint>

#define B_  4
#define L_  2048
#define D_  1024
#define H_  16
#define DK_ 64
#define M_  (B_*L_)   // 8192

// Scratch (device globals — no allocation allowed)
__device__ __half g_Xh[M_*D_];   // fp16-staged activations (reused q/k/v)
__device__ __half g_Wh[D_*D_];   // fp16-staged weight (reused)
__device__ __half g_Qh[M_*D_];
__device__ __half g_Kh[M_*D_];
__device__ __half g_Vh[M_*D_];
__device__ __half g_Aoh[M_*D_]; // attention output (fp16, feeds final GEMM)

__device__ __forceinline__ uint32_t packh2(float a, float b) {
    __half2 h = __floats2half2_rn(a, b);
    return *(uint32_t*)&h;
}
__device__ __forceinline__ uint32_t ld32h(const __half* p) {
    return *(const uint32_t*)p;
}

#define HMMA(C, A0,A1,A2,A3, B0,B1)                                             \
    asm volatile(                                                               \
        "mma.sync.aligned.m16n8k16.row.col.f32.f16.f16.f32 "                    \
        "{%0,%1,%2,%3}, {%4,%5,%6,%7}, {%8,%9}, {%0,%1,%2,%3};"                 \
        : "+f"((C)[0]), "+f"((C)[1]), "+f"((C)[2]), "+f"((C)[3])                \
        : "r"(A0), "r"(A1), "r"(A2), "r"(A3), "r"(B0), "r"(B1))

// ---------------------------------------------------------------------------
// fp32 -> fp16 staging convert (rn)
// ---------------------------------------------------------------------------
__global__ __launch_bounds__(256)
void f32_to_f16(const float4* __restrict__ in, uint2* __restrict__ out, int n4) {
    int i = blockIdx.x * 256 + threadIdx.x;
    if (i < n4) {
        float4 v = in[i];
        uint2 o;
        o.x = packh2(v.x, v.y);
        o.y = packh2(v.z, v.w);
        out[i] = o;
    }
}

// ---------------------------------------------------------------------------
// FP16 tensor-core GEMM: Y[M,N] = Xh[M,K] Wh[N,K]^T + bias  (fp32 accum)
// CTA 128x128, BK=64 halves (128B rows), 256 thr = 8 warps (2m x 4n),
// warp tile 64x32 via 4x4 m16n8k16. cp.async double buffer, pitch 72 halves
// (bank = 4g+tg, conflict-free). Output fp16 (Yh) or fp32 (Yf).
// ---------------------------------------------------------------------------
#define GH_PH      72
#define GH_STAGE_H (128*GH_PH)                 // 9216 halves
#define GH_NST     (D_/64)                     // 16
#define GH_SMEM_BYTES (4*GH_STAGE_H*2)         // 73728

__global__ __launch_bounds__(256, 2)
void gemm_h16(const __half* __restrict__ X, const __half* __restrict__ W,
              const float* __restrict__ bias, __half* __restrict__ Yh,
              float* __restrict__ Yf, float scale) {
    extern __shared__ __half hsm[];
    __half* As = hsm;                    // [2][128][72]
    __half* Bs = hsm + 2 * GH_STAGE_H;   // [2][128][72]

    const int tid  = threadIdx.x;
    const int warp = tid >> 5;
    const int lane = tid & 31;
    const int wm   = warp >> 2;
    const int wn   = warp & 3;
    const int g    = lane >> 2;
    const int tg   = lane & 3;
    const int m0   = blockIdx.y * 128;
    const int n0   = blockIdx.x * 128;

    const int lrow = tid >> 1;           // 0..127
    const int lho  = (tid & 1) * 32;     // halves offset (64B)

    float c[4][4][4];
#pragma unroll
    for (int mt = 0; mt < 4; mt++)
#pragma unroll
        for (int nt = 0; nt < 4; nt++)
#pragma unroll
            for (int e = 0; e < 4; e++) c[mt][nt][e] = 0.f;

#define GH_ISSUE(K0, BUF)                                                        \
    do {                                                                         \
        const __half* _gx = X + (size_t)(m0 + lrow) * D_ + (K0) + lho;           \
        const __half* _gw = W + (size_t)(n0 + lrow) * D_ + (K0) + lho;           \
        uint32_t _sa = (uint32_t)__cvta_generic_to_shared(                        \
            As + (BUF) * GH_STAGE_H + lrow * GH_PH + lho);                       \
        uint32_t _sb = (uint32_t)__cvta_generic_to_shared(                        \
            Bs + (BUF) * GH_STAGE_H + lrow * GH_PH + lho);                       \
        _Pragma("unroll")                                                        \
        for (int _i = 0; _i < 4; _i++) {                                         \
            asm volatile("cp.async.cg.shared.global [%0], [%1], 16;"             \
                         :: "r"(_sa + _i * 16u), "l"(_gx + _i * 8));             \
            asm volatile("cp.async.cg.shared.global [%0], [%1], 16;"             \
                         :: "r"(_sb + _i * 16u), "l"(_gw + _i * 8));             \
        }                                                                        \
        asm volatile("cp.async.commit_group;");                                  \
    } while (0)

    GH_ISSUE(0, 0);

    for (int s = 0; s < GH_NST; s++) {
        const int buf = s & 1;
        asm volatile("cp.async.wait_group 0;");
        __syncthreads();
        if (s + 1 < GH_NST) GH_ISSUE((s + 1) * 64, buf ^ 1);

#pragma unroll
        for (int kc = 0; kc < 4; kc++) {
            const int kk = kc * 16 + 2 * tg;
            uint32_t a[4][4], bb[4][2];
#pragma unroll
            for (int mt = 0; mt < 4; mt++) {
                const __half* Ar = As + buf * GH_STAGE_H +
                                   (wm * 64 + mt * 16 + g) * GH_PH + kk;
                a[mt][0] = ld32h(Ar);
                a[mt][1] = ld32h(Ar + 8 * GH_PH);
                a[mt][2] = ld32h(Ar + 8);
                a[mt][3] = ld32h(Ar + 8 * GH_PH + 8);
            }
#pragma unroll
            for (int nt = 0; nt < 4; nt++) {
                const __half* Br = Bs + buf * GH_STAGE_H +
                                   (wn * 32 + nt * 8 + g) * GH_PH + kk;
                bb[nt][0] = ld32h(Br);
                bb[nt][1] = ld32h(Br + 8);
            }
#pragma unroll
            for (int mt = 0; mt < 4; mt++)
#pragma unroll
                for (int nt = 0; nt < 4; nt++)
                    HMMA(c[mt][nt], a[mt][0], a[mt][1], a[mt][2], a[mt][3],
                         bb[nt][0], bb[nt][1]);
        }
        __syncthreads();
    }
#undef GH_ISSUE

#pragma unroll
    for (int nt = 0; nt < 4; nt++) {
        const int col = n0 + wn * 32 + nt * 8 + tg * 2;
        const float2 bv = *(const float2*)&bias[col];
#pragma unroll
        for (int mt = 0; mt < 4; mt++) {
            const int row = m0 + wm * 64 + mt * 16 + g;
            float o0x = (c[mt][nt][0] + bv.x) * scale;
            float o0y = (c[mt][nt][1] + bv.y) * scale;
            float o1x = (c[mt][nt][2] + bv.x) * scale;
            float o1y = (c[mt][nt][3] + bv.y) * scale;
            if (Yh) {
                *(uint32_t*)(Yh + (size_t)row * D_ + col)       = packh2(o0x, o0y);
                *(uint32_t*)(Yh + (size_t)(row + 8) * D_ + col) = packh2(o1x, o1y);
            } else {
                float2 f0 = {o0x, o0y}, f1 = {o1x, o1y};
                *(float2*)(Yf + (size_t)row * D_ + col)       = f0;
                *(float2*)(Yf + (size_t)(row + 8) * D_ + col) = f1;
            }
        }
    }
}

// ---------------------------------------------------------------------------
// Flash attention, causal, FP16 mma.sync (fp32 softmax + accum).
// Grid (L/128, H, B) reversed qb; 256 thr = 8 warps, warp w: q-rows [16w,16w+16).
// Smem halves: Qs[128][72], Ks[2][64][72], Vs[2][64][72]  (54 KB -> 2 CTA/SM).
// S = Q K^T: A=Qs, B=Ks natural [c][d] (= col-major B). PV: A = P packed from
// S accumulator registers (no shuffle needed in fp16), B via ldmatrix.x4.trans.
// ---------------------------------------------------------------------------
#define FP_PH 72
#define FLASH_SMEM_BYTES ((128*FP_PH + 4*64*FP_PH) * 2)   // 55296

__device__ __forceinline__ float redmax4(float v) {
    v = fmaxf(v, __shfl_xor_sync(0xffffffffu, v, 1));
    v = fmaxf(v, __shfl_xor_sync(0xffffffffu, v, 2));
    return v;
}
__device__ __forceinline__ float redsum4(float v) {
    v += __shfl_xor_sync(0xffffffffu, v, 1);
    v += __shfl_xor_sync(0xffffffffu, v, 2);
    return v;
}

__global__ __launch_bounds__(256, 2)
void flash_h16(const __half* __restrict__ Qp, const __half* __restrict__ Kp,
               const __half* __restrict__ Vp, __half* __restrict__ Ao) {
    extern __shared__ __half hsm[];
    __half* Qs = hsm;                    // [128][72]
    __half* Ks = Qs + 128 * FP_PH;       // [2][64][72]
    __half* Vs = Ks + 2 * 64 * FP_PH;    // [2][64][72]

    const int tid  = threadIdx.x;
    const int warp = tid >> 5;
    const int lane = tid & 31;
    const int g    = lane >> 2;
    const int tg   = lane & 3;
    const int qb   = (int)gridDim.x - 1 - (int)blockIdx.x;
    const int h    = blockIdx.y;
    const int b    = blockIdx.z;

    const int rowbase = b * L_ + qb * 128;
    const int colbase = h * DK_;
    const int wr0     = warp * 16;

    // Q prologue (fp16, pre-scaled upstream): 128 rows x 128B
    {
        const int r  = tid >> 1;
        const int co = (tid & 1) * 32;
        const __half* src = Qp + (size_t)(rowbase + r) * D_ + colbase + co;
        uint32_t dst = (uint32_t)__cvta_generic_to_shared(Qs + r * FP_PH + co);
#pragma unroll
        for (int i = 0; i < 4; i++)
            asm volatile("cp.async.cg.shared.global [%0], [%1], 16;"
                         :: "r"(dst + i * 16u), "l"(src + i * 8));
    }

    const int kvc = tid >> 2;            // key row 0..63
    const int kj  = (tid & 3) * 16;      // halves offset (32B)
#define ISSUE_KV(KB, BUF)                                                        \
    do {                                                                         \
        const size_t _gr = (size_t)(b * L_ + (KB) * 64 + kvc) * D_ + colbase + kj;\
        const __half* _ks = Kp + _gr;                                            \
        const __half* _vs = Vp + _gr;                                            \
        uint32_t _kd = (uint32_t)__cvta_generic_to_shared(                        \
            Ks + (BUF) * 64 * FP_PH + kvc * FP_PH + kj);                         \
        uint32_t _vd = (uint32_t)__cvta_generic_to_shared(                        \
            Vs + (BUF) * 64 * FP_PH + kvc * FP_PH + kj);                         \
        _Pragma("unroll")                                                        \
        for (int _i = 0; _i < 2; _i++) {                                         \
            asm volatile("cp.async.cg.shared.global [%0], [%1], 16;"             \
                         :: "r"(_kd + _i * 16u), "l"(_ks + _i * 8));             \
            asm volatile("cp.async.cg.shared.global [%0], [%1], 16;"             \
                         :: "r"(_vd + _i * 16u), "l"(_vs + _i * 8));             \
        }                                                                        \
    } while (0)

    ISSUE_KV(0, 0);
    asm volatile("cp.async.commit_group;");

    float m0 = -1e30f, m1 = -1e30f, l0 = 0.f, l1 = 0.f;
    float O[8][4];
#pragma unroll
    for (int dt = 0; dt < 8; dt++)
#pragma unroll
        for (int e = 0; e < 4; e++) O[dt][e] = 0.f;

    const int nkb  = 2 * qb + 2;
    const int lrow = lane & 15;          // ldmatrix row provider
    const int lc8  = (lane >> 4) * 8;    // ldmatrix col group

    for (int kb = 0; kb < nkb; kb++) {
        const int buf = kb & 1;
        asm volatile("cp.async.wait_group 0;");
        __syncthreads();
        if (kb + 1 < nkb) ISSUE_KV(kb + 1, buf ^ 1);
        asm volatile("cp.async.commit_group;");

        const __half* Kb = Ks + buf * 64 * FP_PH;
        const __half* Vb = Vs + buf * 64 * FP_PH;

        // ---- S = Q K^T : 4 k16-chunks x 8 n-tiles ----
        float s[8][4];
#pragma unroll
        for (int nt = 0; nt < 8; nt++)
#pragma unroll
            for (int e = 0; e < 4; e++) s[nt][e] = 0.f;

#pragma unroll
        for (int kc = 0; kc < 4; kc++) {
            const int kk = kc * 16 + 2 * tg;
            const __half* Ar = Qs + (wr0 + g) * FP_PH + kk;
            uint32_t a0 = ld32h(Ar);
            uint32_t a1 = ld32h(Ar + 8 * FP_PH);
            uint32_t a2 = ld32h(Ar + 8);
            uint32_t a3 = ld32h(Ar + 8 * FP_PH + 8);
#pragma unroll
            for (int nt = 0; nt < 8; nt++) {
                const __half* Br = Kb + (nt * 8 + g) * FP_PH + kk;
                uint32_t b0 = ld32h(Br);
                uint32_t b1 = ld32h(Br + 8);
                HMMA(s[nt], a0, a1, a2, a3, b0, b1);
            }
        }

        // ---- causal mask ----
        if (kb >= 2 * qb) {
            const int qg0 = qb * 128 + wr0 + g;
            const int qg1 = qg0 + 8;
#pragma unroll
            for (int nt = 0; nt < 8; nt++) {
                const int kg = kb * 64 + nt * 8 + 2 * tg;
                if (kg     > qg0) s[nt][0] = -1e30f;
                if (kg + 1 > qg0) s[nt][1] = -1e30f;
                if (kg     > qg1) s[nt][2] = -1e30f;
                if (kg + 1 > qg1) s[nt][3] = -1e30f;
            }
        }

        // ---- online softmax (fp32); pack P to fp16 A-fragments ----
        uint32_t u0[8], u1[8];
        {
            float mx0 = -1e30f, mx1 = -1e30f;
#pragma unroll
            for (int nt = 0; nt < 8; nt++) {
                mx0 = fmaxf(mx0, fmaxf(s[nt][0], s[nt][1]));
                mx1 = fmaxf(mx1, fmaxf(s[nt][2], s[nt][3]));
            }
            mx0 = redmax4(mx0); mx1 = redmax4(mx1);
            const float mn0 = fmaxf(m0, mx0), mn1 = fmaxf(m1, mx1);
            const float al0 = __expf(m0 - mn0), al1 = __expf(m1 - mn1);

            float sum0 = 0.f, sum1 = 0.f;
#pragma unroll
            for (int nt = 0; nt < 8; nt++) {
                const float e0 = __expf(s[nt][0] - mn0);
                const float e1 = __expf(s[nt][1] - mn0);
                const float e2 = __expf(s[nt][2] - mn1);
                const float e3 = __expf(s[nt][3] - mn1);
                sum0 += e0 + e1; sum1 += e2 + e3;
                u0[nt] = packh2(e0, e1);
                u1[nt] = packh2(e2, e3);
            }
            sum0 = redsum4(sum0); sum1 = redsum4(sum1);
            l0 = l0 * al0 + sum0; l1 = l1 * al1 + sum1;
            m0 = mn0; m1 = mn1;
#pragma unroll
            for (int dt = 0; dt < 8; dt++) {
                O[dt][0] *= al0; O[dt][1] *= al0;
                O[dt][2] *= al1; O[dt][3] *= al1;
            }
        }

        // ---- O += P V : P from regs, V via ldmatrix.x4.trans ----
#pragma unroll
        for (int kc = 0; kc < 4; kc++) {
            const uint32_t a0 = u0[2 * kc];
            const uint32_t a1 = u1[2 * kc];
            const uint32_t a2 = u0[2 * kc + 1];
            const uint32_t a3 = u1[2 * kc + 1];
#pragma unroll
            for (int dtp = 0; dtp < 4; dtp++) {
                uint32_t r0, r1, r2, r3;
                uint32_t addr = (uint32_t)__cvta_generic_to_shared(
                    Vb + (kc * 16 + lrow) * FP_PH + dtp * 16 + lc8);
                asm volatile(
                    "ldmatrix.sync.aligned.m8n8.x4.trans.shared.b16 "
                    "{%0,%1,%2,%3}, [%4];"
                    : "=r"(r0), "=r"(r1), "=r"(r2), "=r"(r3) : "r"(addr));
                HMMA(O[2 * dtp],     a0, a1, a2, a3, r0, r1);
                HMMA(O[2 * dtp + 1], a0, a1, a2, a3, r2, r3);
            }
        }
    }
#undef ISSUE_KV

    // ---- normalize (fp32), write Ao as fp16 ----
    {
        const float inv0 = 1.0f / l0;
        const float inv1 = 1.0f / l1;
        __half* d0 = Ao + (size_t)(rowbase + wr0 + g    ) * D_ + colbase + 2 * tg;
        __half* d1 = Ao + (size_t)(rowbase + wr0 + g + 8) * D_ + colbase + 2 * tg;
#pragma unroll
        for (int dt = 0; dt < 8; dt++) {
            *(uint32_t*)(d0 + dt * 8) = packh2(O[dt][0] * inv0, O[dt][1] * inv0);
            *(uint32_t*)(d1 + dt * 8) = packh2(O[dt][2] * inv1, O[dt][3] * inv1);
        }
    }
}

// ---------------------------------------------------------------------------
extern "C" void kernel_launch(void* const* d_in, const int* in_sizes, int n_in,
                              void* d_out, int out_size) {
    (void)in_sizes; (void)n_in; (void)out_size;
    const float* q    = (const float*)d_in[0];
    const float* k    = (const float*)d_in[1];
    const float* v    = (const float*)d_in[2];
    const float* wq_w = (const float*)d_in[3];
    const float* wq_b = (const float*)d_in[4];
    const float* wk_w = (const float*)d_in[5];
    const float* wk_b = (const float*)d_in[6];
    const float* wv_w = (const float*)d_in[7];
    const float* wv_b = (const float*)d_in[8];
    const float* wo_w = (const float*)d_in[9];
    const float* wo_b = (const float*)d_in[10];

    __half *Xh, *Wh, *Qh, *Kh, *Vh, *Aoh;
    cudaGetSymbolAddress((void**)&Xh,  g_Xh);
    cudaGetSymbolAddress((void**)&Wh,  g_Wh);
    cudaGetSymbolAddress((void**)&Qh,  g_Qh);
    cudaGetSymbolAddress((void**)&Kh,  g_Kh);
    cudaGetSymbolAddress((void**)&Vh,  g_Vh);
    cudaGetSymbolAddress((void**)&Aoh, g_Aoh);

    cudaFuncSetAttribute(gemm_h16,
                         cudaFuncAttributeMaxDynamicSharedMemorySize, GH_SMEM_BYTES);
    cudaFuncSetAttribute(flash_h16,
                         cudaFuncAttributeMaxDynamicSharedMemorySize, FLASH_SMEM_BYTES);

    const int NX4 = M_ * D_ / 4;   // 2M float4
    const int NW4 = D_ * D_ / 4;   // 256K float4
    dim3 gg(D_/128, M_/128);       // (8, 64)

    // Q projection (pre-scaled by 1/sqrt(DK) = 0.125, exact power of two)
    f32_to_f16<<<NX4/256, 256>>>((const float4*)q,    (uint2*)Xh, NX4);
    f32_to_f16<<<NW4/256, 256>>>((const float4*)wq_w, (uint2*)Wh, NW4);
    gemm_h16<<<gg, 256, GH_SMEM_BYTES>>>(Xh, Wh, wq_b, Qh, nullptr, 0.125f);
    // K projection
    f32_to_f16<<<NX4/256, 256>>>((const float4*)k,    (uint2*)Xh, NX4);
    f32_to_f16<<<NW4/256, 256>>>((const float4*)wk_w, (uint2*)Wh, NW4);
    gemm_h16<<<gg, 256, GH_SMEM_BYTES>>>(Xh, Wh, wk_b, Kh, nullptr, 1.0f);
    // V projection
    f32_to_f16<<<NX4/256, 256>>>((const float4*)v,    (uint2*)Xh, NX4);
    f32_to_f16<<<NW4/256, 256>>>((const float4*)wv_w, (uint2*)Wh, NW4);
    gemm_h16<<<gg, 256, GH_SMEM_BYTES>>>(Xh, Wh, wv_b, Vh, nullptr, 1.0f);

    // Attention (fp32 softmax/accum, fp16 operands)
    flash_h16<<<dim3(L_/128, H_, B_), 256, FLASH_SMEM_BYTES>>>(Qh, Kh, Vh, Aoh);

    // Output projection (fp32 result)
    f32_to_f16<<<NW4/256, 256>>>((const float4*)wo_w, (uint2*)Wh, NW4);
    gemm_h16<<<gg, 256, GH_SMEM_BYTES>>>(Aoh, Wh, wo_b, nullptr, (float*)d_out, 1.0f);
}